// round 9
// baseline (speedup 1.0000x reference)
#include <cuda_runtime.h>
#include <cuda_bf16.h>
#include <cstdint>

#define BB 16
#define HH 180
#define WW 240
#define NC (BB*HH*WW)      /* 691200 full-res cells            */
#define HV (HH/2)          /* 90                               */
#define WV (WW/2)          /* 120                              */
#define VPB (HV*WV)        /* 10800 voxels per batch           */
#define NV (BB*VPB)        /* 172800 half-res voxels           */
#define NVP (NV/2)         /* 86400 voxel pairs                */

#define TILE_EV 1024
#define TILE_F4 (TILE_EV * 5 / 4)   /* 1280 float4 = 20 KB smem */

// Scratch (__device__ globals — no allocations allowed)
__device__ float2   g_ct[NC];      // per full-res cell: (count, tsum_raw)
__device__ unsigned g_tmax[BB];    // per-batch max(t) as uint bits (t >= 0)

// ---------------------------------------------------------------------------
__global__ void __launch_bounds__(256) scatter_kernel(
    const float4* __restrict__ evq, int n, int nTiles)
{
    __shared__ float4 sbuf[TILE_F4];
    const float* sf = reinterpret_cast<const float*>(sbuf);

    const unsigned FULL = 0xffffffffu;
    int lane = threadIdx.x & 31;
    unsigned loc = 0;  // lane l (<16) carries running max-bits for batch l

    long long totF4 = (long long)n * 5 / 4;   // n*5 divisible by 4 for n=8M

    for (int tile = blockIdx.x; tile < nTiles; tile += gridDim.x) {
        // ---- coalesced stage: 1280 float4 into smem ----
        long long baseF4 = (long long)tile * TILE_F4;
        #pragma unroll
        for (int q = 0; q < 5; ++q) {
            int idx = threadIdx.x + q * 256;
            long long g = baseF4 + idx;
            if (g < totF4) sbuf[idx] = __ldg(evq + g);
        }
        __syncthreads();

        // ---- process: round-robin map (lane stride = 5 floats, bank-clean) ----
        long long baseEv = (long long)tile * TILE_EV;
        #pragma unroll
        for (int q = 0; q < 4; ++q) {
            int le = threadIdx.x + q * 256;
            long long e = baseEv + le;
            bool valid = (e < (long long)n);
            float x = 0.f, y = 0.f, t = 0.f, b = 0.f;
            if (valid) {
                int s = 5 * le;
                x = sf[s + 0];
                y = sf[s + 1];
                t = sf[s + 2];
                b = sf[s + 4];
            }
            int bi = (int)b, xi = (int)x, yi = (int)y;

            if (valid) {
                // single fused atomic per event: (count, raw t) into full-res cell
                int idx_c = xi + WW * yi + (WW * HH) * bi;
                if ((unsigned)idx_c < (unsigned)NC)
                    asm volatile("red.global.add.v2.f32 [%0], {%1, %2};"
                                 :: "l"(&g_ct[idx_c]), "f"(1.0f), "f"(t) : "memory");
            }

            // per-batch time max: b is sorted, so warps are almost always uniform
            unsigned tb = __float_as_uint(t);         // t >= 0: uint order == float order
            int b0 = __shfl_sync(FULL, bi, 0);
            if (__all_sync(FULL, bi == b0)) {
                unsigned wm = __reduce_max_sync(FULL, tb);
                if (lane == b0) loc = max(loc, wm);
            } else {                                  // boundary warp (rare) fallback
                for (int l = 0; l < 32; ++l) {
                    int      bl = __shfl_sync(FULL, bi, l);
                    unsigned tl = __shfl_sync(FULL, tb, l);
                    if (lane == bl) loc = max(loc, tl);
                }
            }
        }
        __syncthreads();
    }

    __shared__ unsigned smax[BB];
    if (threadIdx.x < BB) smax[threadIdx.x] = 0u;
    __syncthreads();
    if (lane < BB && loc) atomicMax(&smax[lane], loc);
    __syncthreads();
    if (threadIdx.x < BB && smax[threadIdx.x])
        atomicMax(&g_tmax[threadIdx.x], smax[threadIdx.x]);
}

// ---------------------------------------------------------------------------
// One thread per PAIR of adjacent half-res voxels (jj = 2u, 2u+1).
// Pairs never straddle the jj<60 / jj>=60 branch boundary (u<30 <=> both <60),
// so the spill logic stays branch-uniform and all loads/stores vectorize:
//   cells for the pair = two adjacent float4s per row.
// Voxel (k, ii, jj) aggregates, per the reference's
// idx_k = floor(x/2) + 60*y + 10800*b quirk:
//   even row y=2ii, cols [2jj, 2jj+1]                       (always)
//   jj >= 60: odd row y=2ii+1, cols [2jj-120, 2jj-119]      (same batch)
//   jj <  60, ii >= 1: odd row y=2ii-1, cols [120+2jj, 121+2jj]
//   jj <  60, ii == 0, k >= 1: batch k-1, row 179, cols [120+2jj, 121+2jj]
__global__ void __launch_bounds__(256) finalize_kernel(float* __restrict__ out) {
    int vp = blockIdx.x * blockDim.x + threadIdx.x;
    if (vp >= NVP) return;

    float*  cont    = out;
    float*  counter = out + NC;
    float*  timer   = out + NC + NV;
    float*  dxo     = out + NC + 2 * NV;
    float*  dyo     = out + NC + 3 * NV;
    const float4* Cq = reinterpret_cast<const float4*>(g_ct);  // 2 cells per float4

    // pair -> (k, ii, u); voxels v0 = base + 2u, v1 = v0 + 1
    int k  = vp / (VPB / 2);
    int rp = vp - k * (VPB / 2);
    int ii = rp / (WV / 2);
    int u  = rp - ii * (WV / 2);
    int v0 = k * VPB + ii * WV + 2 * u;

    int re = k * (HH * WW) + (2 * ii) * WW + 4 * u;   // even-row first cell (mult of 4... even)
    int ro = re + WW;

    // 4 cells per row for the pair: two adjacent float4s
    float4 ea = Cq[(re >> 1) + 0];   // cells re, re+1   -> voxel v0 even-row
    float4 eb = Cq[(re >> 1) + 1];   // cells re+2, re+3 -> voxel v1 even-row
    float4 oa = Cq[(ro >> 1) + 0];
    float4 ob = Cq[(ro >> 1) + 1];

    // container (full-res counts): float4 store per row
    reinterpret_cast<float4*>(cont + re)[0] = make_float4(ea.x, ea.z, eb.x, eb.z);
    reinterpret_cast<float4*>(cont + ro)[0] = make_float4(oa.x, oa.z, ob.x, ob.z);

    // strided diffs
    reinterpret_cast<float2*>(dxo + v0)[0] =
        make_float2((oa.x - oa.z) + (ea.x - ea.z), (ob.x - ob.z) + (eb.x - eb.z));
    reinterpret_cast<float2*>(dyo + v0)[0] =
        make_float2((ea.x - oa.x) + (ea.z - oa.z), (eb.x - ob.x) + (eb.z - ob.z));

    float Tk = __uint_as_float(g_tmax[k]);
    if (Tk == 0.0f) Tk = 1.0f;

    float cnt0 = ea.x + ea.z, ts0 = ea.y + ea.w;
    float cnt1 = eb.x + eb.z, ts1 = eb.y + eb.w;
    float tn0, tn1;

    if (u >= WV / 4) {               // both voxels have jj >= 60
        // odd row y=2ii+1, cells (ro-120 .. ro-117): two adjacent float4s
        float4 xa = Cq[((ro - 120) >> 1) + 0];
        float4 xb = Cq[((ro - 120) >> 1) + 1];
        cnt0 += xa.x + xa.z;  ts0 += xa.y + xa.w;
        cnt1 += xb.x + xb.z;  ts1 += xb.y + xb.w;
        tn0 = ts0 / Tk;  tn1 = ts1 / Tk;
    } else if (ii >= 1) {            // both jj < 60, interior row
        float4 xa = Cq[((re - 120) >> 1) + 0];
        float4 xb = Cq[((re - 120) >> 1) + 1];
        cnt0 += xa.x + xa.z;  ts0 += xa.y + xa.w;
        cnt1 += xb.x + xb.z;  ts1 += xb.y + xb.w;
        tn0 = ts0 / Tk;  tn1 = ts1 / Tk;
    } else {                         // ii == 0, jj < 60: inflow from batch k-1 row 179
        tn0 = ts0 / Tk;  tn1 = ts1 / Tk;
        if (k > 0) {
            int sp = (k - 1) * (HH * WW) + (HH - 1) * WW + 120 + 4 * u;  // even
            float4 xa = Cq[(sp >> 1) + 0];
            float4 xb = Cq[(sp >> 1) + 1];
            float Tp = __uint_as_float(g_tmax[k - 1]);
            if (Tp == 0.0f) Tp = 1.0f;
            cnt0 += xa.x + xa.z;  tn0 += (xa.y + xa.w) / Tp;
            cnt1 += xb.x + xb.z;  tn1 += (xb.y + xb.w) / Tp;
        }
    }

    reinterpret_cast<float2*>(counter + v0)[0] = make_float2(cnt0, cnt1);
    reinterpret_cast<float2*>(timer + v0)[0] = make_float2(
        tn0 / (cnt0 == 0.0f ? 1.0f : cnt0),
        tn1 / (cnt1 == 0.0f ? 1.0f : cnt1));
}

// ---------------------------------------------------------------------------
extern "C" void kernel_launch(void* const* d_in, const int* in_sizes, int n_in,
                              void* d_out, int out_size)
{
    const float* ev = (const float*)d_in[0];
    int n = in_sizes[0] / 5;
    float* out = (float*)d_out;

    // zero scratch via memset nodes
    void* p_ct = nullptr;  cudaGetSymbolAddress(&p_ct, g_ct);
    void* p_tm = nullptr;  cudaGetSymbolAddress(&p_tm, g_tmax);
    cudaMemsetAsync(p_ct, 0, sizeof(float2) * NC);
    cudaMemsetAsync(p_tm, 0, sizeof(unsigned) * BB);

    int nTiles = (n + TILE_EV - 1) / TILE_EV;
    scatter_kernel<<<1184, 256>>>((const float4*)ev, n, nTiles);
    finalize_kernel<<<(NVP + 255) / 256, 256>>>(out);
}